// round 16
// baseline (speedup 1.0000x reference)
#include <cuda_runtime.h>
#include <cuda_fp16.h>
#include <math.h>
#include <stdint.h>

#define S_TOK   4096
#define D_INNER 320
#define HEADS   8
#define DHEAD   40
#define CTX_LEN 77
#define CTX_DIM 768
#define FF_IN   2560
#define FF_HALF 1280
#define ATT_SCALE 0.15811388300841897f
#define QSCALE_L2E (0.15811388300841897f * 1.4426950408889634f)

// ---------------- scratch ----------------
__device__ float  g_h  [S_TOK * D_INNER];          // fp32 residual stream
__device__ __half g_hh [S_TOK * D_INNER];
__device__ __half g_gn [S_TOK * D_INNER];
__device__ __half g_hn [S_TOK * D_INNER];
__device__ __half g_q  [S_TOK * D_INNER];
__device__ __half g_k  [S_TOK * D_INNER];
__device__ __half g_v  [S_TOK * D_INNER];
__device__ __half g_at [S_TOK * D_INNER];
__device__ __half g_act[S_TOK * FF_HALF];
__device__ __half g_k2 [CTX_LEN * D_INNER];
__device__ __half g_v2 [CTX_LEN * D_INNER];
__device__ __half g_wTh[2539520];                  // all weights half, [n][k]
__device__ float  g_gnp[512];                      // groupnorm partials

#define MMA_F16(c, a, b) \
    asm volatile("mma.sync.aligned.m16n8k16.row.col.f32.f16.f16.f32 " \
                 "{%0,%1,%2,%3},{%4,%5,%6,%7},{%8,%9},{%0,%1,%2,%3};" \
                 : "+f"((c)[0]), "+f"((c)[1]), "+f"((c)[2]), "+f"((c)[3]) \
                 : "r"((a)[0]), "r"((a)[1]), "r"((a)[2]), "r"((a)[3]), \
                   "r"((b)[0]), "r"((b)[1]))

#define MMA_F16_K8(c, a0, a1, b0) \
    asm volatile("mma.sync.aligned.m16n8k8.row.col.f32.f16.f16.f32 " \
                 "{%0,%1,%2,%3},{%4,%5},{%6},{%0,%1,%2,%3};" \
                 : "+f"((c)[0]), "+f"((c)[1]), "+f"((c)[2]), "+f"((c)[3]) \
                 : "r"(a0), "r"(a1), "r"(b0))

#define LDMX4(r0, r1, r2, r3, addr) \
    asm volatile("ldmatrix.sync.aligned.m8n8.x4.shared.b16 {%0,%1,%2,%3}, [%4];" \
                 : "=r"(r0), "=r"(r1), "=r"(r2), "=r"(r3) : "r"(addr))
#define LDMX2(r0, r1, addr) \
    asm volatile("ldmatrix.sync.aligned.m8n8.x2.shared.b16 {%0,%1}, [%2];" \
                 : "=r"(r0), "=r"(r1) : "r"(addr))
#define LDMX4T(r0, r1, r2, r3, addr) \
    asm volatile("ldmatrix.sync.aligned.m8n8.x4.trans.shared.b16 {%0,%1,%2,%3}, [%4];" \
                 : "=r"(r0), "=r"(r1), "=r"(r2), "=r"(r3) : "r"(addr))
#define LDMX2T(r0, r1, addr) \
    asm volatile("ldmatrix.sync.aligned.m8n8.x2.trans.shared.b16 {%0,%1}, [%2];" \
                 : "=r"(r0), "=r"(r1) : "r"(addr))

__device__ __forceinline__ void cp_async16(uint32_t s, const void* g) {
    asm volatile("cp.async.cg.shared.global [%0], [%1], 16;" :: "r"(s), "l"(g));
}
__device__ __forceinline__ void cp_commit() {
    asm volatile("cp.async.commit_group;");
}
template<int W> __device__ __forceinline__ void cp_wait() {
    asm volatile("cp.async.wait_group %0;" :: "n"(W));
}
__device__ __forceinline__ uint32_t smem_u32(const void* p) {
    return (uint32_t)__cvta_generic_to_shared(p);
}

// ---------------- weight transpose + fp32->half (flat tile grid) -------------
struct TDesc { const float* src; __half* dst; int K; int N; };
struct TArgs { TDesc d[12]; int off[13]; };

__global__ void transpose_all_kernel(TArgs a)
{
    int b = blockIdx.x;
    int s = 0;
    #pragma unroll
    for (int i = 0; i < 12; i++)
        if (b >= a.off[i + 1]) s = i + 1;
    TDesc t = a.d[s];
    int local = b - a.off[s];
    int tilesx = (t.N + 31) >> 5;
    int bx = local % tilesx;
    int by = local / tilesx;

    __shared__ float tile[32][33];
    int tx = threadIdx.x, ty = threadIdx.y;
    int x = bx * 32 + tx;
    int y0 = by * 32;
    #pragma unroll
    for (int j = 0; j < 4; j++) {
        int y = y0 + ty + j * 8;
        if (y < t.K && x < t.N)
            tile[ty + j * 8][tx] = t.src[(size_t)y * t.N + x];
    }
    __syncthreads();
    int x2 = by * 32 + tx;
    int y20 = bx * 32;
    #pragma unroll
    for (int j = 0; j < 4; j++) {
        int y2 = y20 + ty + j * 8;
        if (y2 < t.N && x2 < t.K)
            t.dst[(size_t)y2 * t.K + x2] = __float2half(tile[tx][ty + j * 8]);
    }
}

// ---------------- GroupNorm split: partial sums + apply ----------------------
__global__ void gn_part_kernel(const float* __restrict__ x)
{
    const int g = blockIdx.x, b = blockIdx.y;
    const float4* p = reinterpret_cast<const float4*>(x + g * 10 * S_TOK + b * 5120);
    float s = 0.f, sq = 0.f;
    #pragma unroll
    for (int i = 0; i < 5; i++) {
        float4 v = p[threadIdx.x + i * 256];
        s  += v.x + v.y + v.z + v.w;
        sq += v.x * v.x + v.y * v.y + v.z * v.z + v.w * v.w;
    }
    __shared__ float ss[256], sk[256];
    ss[threadIdx.x] = s; sk[threadIdx.x] = sq;
    __syncthreads();
    for (int off = 128; off > 0; off >>= 1) {
        if (threadIdx.x < off) {
            ss[threadIdx.x] += ss[threadIdx.x + off];
            sk[threadIdx.x] += sk[threadIdx.x + off];
        }
        __syncthreads();
    }
    if (threadIdx.x == 0) {
        g_gnp[(g * 8 + b) * 2]     = ss[0];
        g_gnp[(g * 8 + b) * 2 + 1] = sk[0];
    }
}

__global__ void gn_apply_kernel(const float* __restrict__ x,
                                const float* __restrict__ scale,
                                const float* __restrict__ bias,
                                __half* __restrict__ outT)
{
    const int g = blockIdx.x, b = blockIdx.y;
    float s = 0.f, sq = 0.f;
    #pragma unroll
    for (int i = 0; i < 8; i++) {
        s  += g_gnp[(g * 8 + i) * 2];
        sq += g_gnp[(g * 8 + i) * 2 + 1];
    }
    const float mean = s / 40960.f;
    const float rstd = rsqrtf(sq / 40960.f - mean * mean + 1e-6f);
    const int base = g * 10 * S_TOK + b * 5120;
    const float4* p = reinterpret_cast<const float4*>(x + base);
    #pragma unroll
    for (int i = 0; i < 5; i++) {
        int ii = threadIdx.x + i * 256;
        float4 v = p[ii];
        int idx = base + ii * 4;
        int c = idx >> 12;
        int sp = idx & 4095;
        float sc = scale[c], bi = bias[c];
        outT[(sp + 0) * D_INNER + c] = __float2half((v.x - mean) * rstd * sc + bi);
        outT[(sp + 1) * D_INNER + c] = __float2half((v.y - mean) * rstd * sc + bi);
        outT[(sp + 2) * D_INNER + c] = __float2half((v.z - mean) * rstd * sc + bi);
        outT[(sp + 3) * D_INNER + c] = __float2half((v.w - mean) * rstd * sc + bi);
    }
}

// ---------------- LayerNorm ----------------
__global__ void layernorm_kernel(const float* __restrict__ in,
                                 const float* __restrict__ s,
                                 const float* __restrict__ b,
                                 __half* __restrict__ out)
{
    int row = blockIdx.x * 8 + (threadIdx.x >> 5);
    int lane = threadIdx.x & 31;
    const float2* xr = reinterpret_cast<const float2*>(in + row * D_INNER);
    float2 v[5];
    float sum = 0.f, sq = 0.f;
    #pragma unroll
    for (int i = 0; i < 5; i++) {
        v[i] = xr[lane + i * 32];
        sum += v[i].x + v[i].y;
        sq  += v[i].x * v[i].x + v[i].y * v[i].y;
    }
    #pragma unroll
    for (int off = 16; off > 0; off >>= 1) {
        sum += __shfl_xor_sync(0xffffffffu, sum, off);
        sq  += __shfl_xor_sync(0xffffffffu, sq,  off);
    }
    float mean = sum / (float)D_INNER;
    float var  = sq / (float)D_INNER - mean * mean;
    float rstd = rsqrtf(var + 1e-5f);
    __half2* orow = reinterpret_cast<__half2*>(out + row * D_INNER);
    #pragma unroll
    for (int i = 0; i < 5; i++) {
        int j = (lane + i * 32) * 2;
        float y0 = (v[i].x - mean) * rstd * s[j]     + b[j];
        float y1 = (v[i].y - mean) * rstd * s[j + 1] + b[j + 1];
        orow[lane + i * 32] = __floats2half2_rn(y0, y1);
    }
}

// ---------------- fp16 GEMM: 64x64x32, 128 thr (R11 config) ------------------
#define GBM 64
#define GBN 64
#define GBK 32
#define STG 2560
#define GEMM_SMEM_BYTES (6 * STG * 2)

__device__ __forceinline__ void gemm_core(
    const __half* __restrict__ A, const __half* __restrict__ BT,
    const float* __restrict__ bias, const float* __restrict__ resid,
    float* __restrict__ C32, __half* __restrict__ C16,
    int M, int N, int K, int flags, int bm, int bn, float oscale)
{
    extern __shared__ __half smh[];
    const int tid = threadIdx.x;
    const int warp = tid >> 5, lane = tid & 31;
    const int wm = (warp >> 1) * 32, wn = (warp & 1) * 32;
    const int gid = lane >> 2, tig = lane & 3;

    float c[2][4][4];
    #pragma unroll
    for (int i = 0; i < 2; i++)
        #pragma unroll
        for (int j = 0; j < 4; j++)
            #pragma unroll
            for (int t = 0; t < 4; t++) c[i][j][t] = 0.f;

    const int nk = K / GBK;
    const int lr = tid >> 2;
    const int lc = (tid & 3) * 8;

    auto load_stage = [&](int s, int k0) {
        #pragma unroll
        for (int i = 0; i < 2; i++) {
            int r = lr + i * 32;
            cp_async16(smem_u32(&smh[s * STG + r * 40 + lc]),
                       A + (size_t)(bm + r) * K + k0 + lc);
        }
        #pragma unroll
        for (int i = 0; i < 2; i++) {
            int r = lr + i * 32;
            cp_async16(smem_u32(&smh[3 * STG + s * STG + r * 40 + lc]),
                       BT + (size_t)(bn + r) * K + k0 + lc);
        }
    };

    load_stage(0, 0); cp_commit();
    load_stage(1, GBK); cp_commit();

    const int a_row = wm + (lane & 15);
    const int koff  = (lane >> 4) * 8;

    for (int t = 0; t < nk; t++) {
        cp_wait<1>();
        __syncthreads();
        if (t + 2 < nk) load_stage((t + 2) % 3, (t + 2) * GBK);
        cp_commit();

        const int s = t % 3;
        __half* as = &smh[s * STG];
        __half* bs = &smh[3 * STG + s * STG];

        #pragma unroll
        for (int ks = 0; ks < 2; ks++) {
            uint32_t af[2][4], bf[4][2];
            #pragma unroll
            for (int mt = 0; mt < 2; mt++) {
                uint32_t addr = smem_u32(&as[(a_row + mt * 16) * 40 + ks * 16 + koff]);
                LDMX4(af[mt][0], af[mt][1], af[mt][2], af[mt][3], addr);
            }
            #pragma unroll
            for (int p = 0; p < 2; p++) {
                uint32_t r0, r1, r2, r3;
                uint32_t addr = smem_u32(&bs[(wn + p * 16 + (lane & 15)) * 40 + ks * 16 + koff]);
                LDMX4(r0, r1, r2, r3, addr);
                bf[2 * p][0]     = r0; bf[2 * p][1]     = r2;
                bf[2 * p + 1][0] = r1; bf[2 * p + 1][1] = r3;
            }
            #pragma unroll
            for (int mt = 0; mt < 2; mt++)
                #pragma unroll
                for (int nt = 0; nt < 4; nt++)
                    MMA_F16(c[mt][nt], af[mt], bf[nt]);
        }
    }

    #pragma unroll
    for (int mt = 0; mt < 2; mt++) {
        int r0 = bm + wm + mt * 16 + gid;
        int r1 = r0 + 8;
        #pragma unroll
        for (int nt = 0; nt < 4; nt++) {
            int col = bn + wn + nt * 8 + tig * 2;
            float v00 = c[mt][nt][0], v01 = c[mt][nt][1];
            float v10 = c[mt][nt][2], v11 = c[mt][nt][3];
            if (bias) {
                float b0 = bias[col], b1 = bias[col + 1];
                v00 += b0; v01 += b1; v10 += b0; v11 += b1;
            }
            if (flags & 2) {
                v00 *= oscale; v01 *= oscale; v10 *= oscale; v11 *= oscale;
                *reinterpret_cast<__half2*>(&C16[(size_t)r0 * N + col]) = __floats2half2_rn(v00, v01);
                *reinterpret_cast<__half2*>(&C16[(size_t)r1 * N + col]) = __floats2half2_rn(v10, v11);
            } else if (flags & 1) {
                if (resid) {
                    v00 += resid[(size_t)col * M + r0];
                    v01 += resid[(size_t)(col + 1) * M + r0];
                    v10 += resid[(size_t)col * M + r1];
                    v11 += resid[(size_t)(col + 1) * M + r1];
                }
                C32[(size_t)col * M + r0]       = v00;
                C32[(size_t)(col + 1) * M + r0] = v01;
                C32[(size_t)col * M + r1]       = v10;
                C32[(size_t)(col + 1) * M + r1] = v11;
            } else {
                if (resid) {
                    v00 += resid[(size_t)r0 * N + col];
                    v01 += resid[(size_t)r0 * N + col + 1];
                    v10 += resid[(size_t)r1 * N + col];
                    v11 += resid[(size_t)r1 * N + col + 1];
                }
                C32[(size_t)r0 * N + col]     = v00;
                C32[(size_t)r0 * N + col + 1] = v01;
                C32[(size_t)r1 * N + col]     = v10;
                C32[(size_t)r1 * N + col + 1] = v11;
                if (flags & 4) {
                    *reinterpret_cast<__half2*>(&C16[(size_t)r0 * N + col]) = __floats2half2_rn(v00, v01);
                    *reinterpret_cast<__half2*>(&C16[(size_t)r1 * N + col]) = __floats2half2_rn(v10, v11);
                }
            }
        }
    }
}

__global__ __launch_bounds__(128)
void gemm_f16_kernel(const __half* __restrict__ A, const __half* __restrict__ BT,
                     const float* __restrict__ bias, const float* __restrict__ resid,
                     float* __restrict__ C32, __half* __restrict__ C16,
                     int M, int N, int K, int flags)
{
    gemm_core(A, BT, bias, resid, C32, C16, M, N, K, flags,
              blockIdx.y * GBM, blockIdx.x * GBN, 1.0f);
}

__global__ __launch_bounds__(128)
void gemm_qkv_kernel(const __half* __restrict__ A,
                     const __half* __restrict__ B0, const __half* __restrict__ B1,
                     const __half* __restrict__ B2,
                     __half* __restrict__ C0, __half* __restrict__ C1,
                     __half* __restrict__ C2, int M, int N, int K)
{
    const __half* B = (blockIdx.z == 0) ? B0 : (blockIdx.z == 1) ? B1 : B2;
    __half* C       = (blockIdx.z == 0) ? C0 : (blockIdx.z == 1) ? C1 : C2;
    float oscale    = (blockIdx.z == 0) ? QSCALE_L2E : 1.0f;
    gemm_core(A, B, nullptr, nullptr, nullptr, C, M, N, K, 2,
              blockIdx.y * GBM, blockIdx.x * GBN, oscale);
}

// ---------------- fused ff1 + GEGLU (128 thr) --------------------------------
#define FF1_SMEM_BYTES (9 * STG * 2)
__global__ __launch_bounds__(128)
void gemm_ff1g_kernel(const __half* __restrict__ A, const __half* __restrict__ BT,
                      const float* __restrict__ bias, __half* __restrict__ act,
                      int M, int K)
{
    extern __shared__ __half smh[];
    const int bm = blockIdx.y * GBM;
    const int bn = blockIdx.x * GBN;
    const int tid = threadIdx.x;
    const int warp = tid >> 5, lane = tid & 31;
    const int wm = (warp >> 1) * 32, wn = (warp & 1) * 32;
    const int gid = lane >> 2, tig = lane & 3;

    float ca[2][4][4], cg[2][4][4];
    #pragma unroll
    for (int i = 0; i < 2; i++)
        #pragma unroll
        for (int j = 0; j < 4; j++)
            #pragma unroll
            for (int t = 0; t < 4; t++) { ca[i][j][t] = 0.f; cg[i][j][t] = 0.f; }

    const int nk = K / GBK;
    const int lr = tid >> 2;
    const int lc = (tid & 3) * 8;

    auto load_stage = [&](int s, int k0) {
        #pragma unroll
        for (int i = 0; i < 2; i++) {
            int r = lr + i * 32;
            cp_async16(smem_u32(&smh[s * STG + r * 40 + lc]),
                       A + (size_t)(bm + r) * K + k0 + lc);
            cp_async16(smem_u32(&smh[3 * STG + s * STG + r * 40 + lc]),
                       BT + (size_t)(bn + r) * K + k0 + lc);
            cp_async16(smem_u32(&smh[6 * STG + s * STG + r * 40 + lc]),
                       BT + (size_t)(FF_HALF + bn + r) * K + k0 + lc);
        }
    };

    load_stage(0, 0); cp_commit();
    load_stage(1, GBK); cp_commit();

    const int a_row = wm + (lane & 15);
    const int koff  = (lane >> 4) * 8;

    for (int t = 0; t < nk; t++) {
        cp_wait<1>();
        __syncthreads();
        if (t + 2 < nk) load_stage((t + 2) % 3, (t + 2) * GBK);
        cp_commit();

        const int s = t % 3;
        __half* as  = &smh[s * STG];
        __half* bsa = &smh[3 * STG + s * STG];
        __half* bsg = &smh[6 * STG + s * STG];

        #pragma unroll
        for (int ks = 0; ks < 2; ks++) {
            uint32_t af[2][4], bfa[4][2], bfg[4][2];
            #pragma unroll
            for (int mt = 0; mt < 2; mt++) {
                uint32_t addr = smem_u32(&as[(a_row + mt * 16) * 40 + ks * 16 + koff]);
                LDMX4(af[mt][0], af[mt][1], af[mt][2], af[mt][3], addr);
            }
            #pragma unroll
            for (int p = 0; p < 2; p++) {
                uint32_t r0, r1, r2, r3;
                uint32_t addr = smem_u32(&bsa[(wn + p * 16 + (lane & 15)) * 40 + ks * 16 + koff]);
                LDMX4(r0, r1, r2, r3, addr);
                bfa[2 * p][0] = r0; bfa[2 * p][1] = r2;
                bfa[2 * p + 1][0] = r1; bfa[2 * p + 1][1] = r3;
                addr = smem_u32(&bsg[(wn + p * 16 + (lane & 15)) * 40 + ks * 16 + koff]);
                LDMX4(r0, r1, r2, r3, addr);
                bfg[2 * p][0] = r0; bfg[2 * p][1] = r2;
                bfg[2 * p + 1][0] = r1; bfg[2 * p + 1][1] = r3;
            }
            #pragma unroll
            for (int mt = 0; mt < 2; mt++)
                #pragma unroll
                for (int nt = 0; nt < 4; nt++) {
                    MMA_F16(ca[mt][nt], af[mt], bfa[nt]);
                    MMA_F16(cg[mt][nt], af[mt], bfg[nt]);
                }
        }
    }

    #pragma unroll
    for (int mt = 0; mt < 2; mt++) {
        int r0 = bm + wm + mt * 16 + gid;
        int r1 = r0 + 8;
        #pragma unroll
        for (int nt = 0; nt < 4; nt++) {
            int col = bn + wn + nt * 8 + tig * 2;
            float ba0 = bias[col], ba1 = bias[col + 1];
            float bg0 = bias[FF_HALF + col], bg1 = bias[FF_HALF + col + 1];
            float a00 = ca[mt][nt][0] + ba0, a01 = ca[mt][nt][1] + ba1;
            float a10 = ca[mt][nt][2] + ba0, a11 = ca[mt][nt][3] + ba1;
            float g00 = cg[mt][nt][0] + bg0, g01 = cg[mt][nt][1] + bg1;
            float g10 = cg[mt][nt][2] + bg0, g11 = cg[mt][nt][3] + bg1;
            const float inv_s2 = 0.70710678118654752f;
            float e00 = 0.5f * g00 * (1.f + erff(g00 * inv_s2));
            float e01 = 0.5f * g01 * (1.f + erff(g01 * inv_s2));
            float e10 = 0.5f * g10 * (1.f + erff(g10 * inv_s2));
            float e11 = 0.5f * g11 * (1.f + erff(g11 * inv_s2));
            *reinterpret_cast<__half2*>(&act[(size_t)r0 * FF_HALF + col]) =
                __floats2half2_rn(a00 * e00, a01 * e01);
            *reinterpret_cast<__half2*>(&act[(size_t)r1 * FF_HALF + col]) =
                __floats2half2_rn(a10 * e10, a11 * e11);
        }
    }
}

// ---------------- fp32 SGEMM for ctx K/V (small M=77), half out -------------
#define BM 64
#define BN 64
#define BKK 16
__global__ __launch_bounds__(256)
void sgemm_ctx_kernel(const float* __restrict__ A,
                      const float* __restrict__ B0, const float* __restrict__ B1,
                      __half* __restrict__ C0, __half* __restrict__ C1,
                      int M, int N, int K)
{
    const float* B = (blockIdx.z == 0) ? B0 : B1;
    __half* C      = (blockIdx.z == 0) ? C0 : C1;
    __shared__ float As[BKK][BM];
    __shared__ float Bs[BKK][BN];
    const int bm = blockIdx.y * BM;
    const int bn = blockIdx.x * BN;
    const int tid = threadIdx.x;
    const int tx = tid & 15;
    const int ty = tid >> 4;
    const int arow = tid >> 2;
    const int acol = (tid & 3) * 4;
    const int brow = tid >> 4;
    const int bcol = (tid & 15) * 4;

    float acc[4][4];
    #pragma unroll
    for (int i = 0; i < 4; i++)
        #pragma unroll
        for (int j = 0; j < 4; j++) acc[i][j] = 0.f;

    for (int k0 = 0; k0 < K; k0 += BKK) {
        float4 av = make_float4(0.f, 0.f, 0.f, 0.f);
        if (bm + arow < M)
            av = *reinterpret_cast<const float4*>(A + (size_t)(bm + arow) * K + k0 + acol);
        As[acol + 0][arow] = av.x;
        As[acol + 1][arow] = av.y;
        As[acol + 2][arow] = av.z;
        As[acol + 3][arow] = av.w;
        float4 bv = *reinterpret_cast<const float4*>(B + (size_t)(k0 + brow) * N + bn + bcol);
        *reinterpret_cast<float4*>(&Bs[brow][bcol]) = bv;
        __syncthreads();
        #pragma unroll
        for (int kk = 0; kk < BKK; kk++) {
            float4 a4 = *reinterpret_cast<const float4*>(&As[kk][ty * 4]);
            float4 b4 = *reinterpret_cast<const float4*>(&Bs[kk][tx * 4]);
            float a[4] = {a4.x, a4.y, a4.z, a4.w};
            float b[4] = {b4.x, b4.y, b4.z, b4.w};
            #pragma unroll
            for (int i = 0; i < 4; i++)
                #pragma unroll
                for (int j = 0; j < 4; j++)
                    acc[i][j] += a[i] * b[j];
        }
        __syncthreads();
    }

    #pragma unroll
    for (int i = 0; i < 4; i++) {
        int m = bm + ty * 4 + i;
        if (m >= M) continue;
        #pragma unroll
        for (int j = 0; j < 4; j++)
            C[(size_t)m * N + bn + tx * 4 + j] = __float2half(acc[i][j]);
    }
}

// ---------------- self-attention: flash fp16, register P, h2exp2 softmax -----
#define KS_STG 3584
#define VS_BASE 7168
#define ATTN_SMEM_BYTES (14336 * 2)

__global__ __launch_bounds__(256, 2)
void attn_self_f16_kernel(const __half* __restrict__ q, const __half* __restrict__ k,
                          const __half* __restrict__ v, __half* __restrict__ o)
{
    extern __shared__ __half smh[];

    const int h = blockIdx.y;
    const int q0 = blockIdx.x * 128;
    const int tid = threadIdx.x;
    const int warp = tid >> 5, lane = tid & 31;
    const int gid = lane >> 2, tig = lane & 3;

    uint32_t qf16[2][4], qf8[2];
    {
        const __half* qp0 = q + (size_t)(q0 + warp * 16 + gid) * D_INNER + h * 40;
        const __half* qp1 = qp0 + 8 * D_INNER;
        #pragma unroll
        for (int s = 0; s < 2; s++) {
            qf16[s][0] = *reinterpret_cast<const uint32_t*>(qp0 + s * 16 + 2 * tig);
            qf16[s][1] = *reinterpret_cast<const uint32_t*>(qp1 + s * 16 + 2 * tig);
            qf16[s][2] = *reinterpret_cast<const uint32_t*>(qp0 + s * 16 + 8 + 2 * tig);
            qf16[s][3] = *reinterpret_cast<const uint32_t*>(qp1 + s * 16 + 8 + 2 * tig);
        }
        qf8[0] = *reinterpret_cast<const uint32_t*>(qp0 + 32 + 2 * tig);
        qf8[1] = *reinterpret_cast<const uint32_t*>(qp1 + 32 + 2 * tig);
    }

    float oacc[5][4];
    #pragma unroll
    for (int nt = 0; nt < 5; nt++)
        #pragma unroll
        for (int t = 0; t < 4; t++) oacc[nt][t] = 0.f;
    float m0 = -1e30f, m1 = -1e30f, l0 = 0.f, l1 = 0.f;

    auto load_tile = [&](int buf, int t0) {
        #pragma unroll
        for (int j = 0; j < 2; j++) {
            int i = tid + j * 256;
            if (i < 320) {
                int row = i / 5;
                int c8 = (i - row * 5) * 8;
                size_t gi = (size_t)(t0 + row) * D_INNER + h * 40 + c8;
                cp_async16(smem_u32(&smh[buf * KS_STG + row * 56 + c8]), k + gi);
                cp_async16(smem_u32(&smh[VS_BASE + buf * KS_STG + row * 56 + c8]), v + gi);
            }
        }
    };

    load_tile(0, 0); cp_commit();

    const int NTILES = S_TOK / 64;
    for (int t = 0; t < NTILES; t++) {
        cp_wait<0>();
        __syncthreads();
        if (t + 1 < NTILES) load_tile((t + 1) & 1, (t + 1) * 64);
        cp_commit();

        const __half* ks_ = &smh[(t & 1) * KS_STG];
        const __half* vs_ = &smh[VS_BASE + (t & 1) * KS_STG];

        float sc[8][4];
        #pragma unroll
        for (int nt = 0; nt < 8; nt++)
            #pragma unroll
            for (int e = 0; e < 4; e++) sc[nt][e] = 0.f;

        const int krow16 = lane & 15;
        const int koff   = (lane >> 4) << 3;
        const int krow8  = (lane & 7) + ((lane >> 3) & 1) * 8;
        #pragma unroll
        for (int p = 0; p < 4; p++) {
            #pragma unroll
            for (int s = 0; s < 2; s++) {
                uint32_t r0, r1, r2, r3;
                uint32_t addr = smem_u32(&ks_[(p * 16 + krow16) * 56 + s * 16 + koff]);
                LDMX4(r0, r1, r2, r3, addr);
                uint32_t b0[2] = {r0, r2}, b1[2] = {r1, r3};
                MMA_F16(sc[2 * p],     qf16[s], b0);
                MMA_F16(sc[2 * p + 1], qf16[s], b1);
            }
            uint32_t r0, r1;
            uint32_t addr = smem_u32(&ks_[(p * 16 + krow8) * 56 + 32]);
            LDMX2(r0, r1, addr);
            MMA_F16_K8(sc[2 * p],     qf8[0], qf8[1], r0);
            MMA_F16_K8(sc[2 * p + 1], qf8[0], qf8[1], r1);
        }

        float t0m = -1e30f, t1m = -1e30f;
        #pragma unroll
        for (int nt = 0; nt < 8; nt++) {
            t0m = fmaxf(t0m, fmaxf(sc[nt][0], sc[nt][1]));
            t1m = fmaxf(t1m, fmaxf(sc[nt][2], sc[nt][3]));
        }
        t0m = fmaxf(t0m, __shfl_xor_sync(0xffffffffu, t0m, 1));
        t0m = fmaxf(t0m, __shfl_xor_sync(0xffffffffu, t0m, 2));
        t1m = fmaxf(t1m, __shfl_xor_sync(0xffffffffu, t1m, 1));
        t1m = fmaxf(t1m, __shfl_xor_sync(0xffffffffu, t1m, 2));

        float mn0 = fmaxf(m0, t0m), mn1 = fmaxf(m1, t1m);
        float corr0 = exp2f(m0 - mn0), corr1 = exp2f(m1 - mn1);
        float sum0 = 0.f, sum1 = 0.f;
        uint32_t pf[8][2];
        #pragma unroll
        for (int nt = 0; nt < 8; nt++) {
            // rows gid (c0,c1) and gid+8 (c2,c3): pack deltas, single f16x2 exp
            __half2 d0 = __floats2half2_rn(sc[nt][0] - mn0, sc[nt][1] - mn0);
            __half2 d1 = __floats2half2_rn(sc[nt][2] - mn1, sc[nt][3] - mn1);
            __half2 p0 = h2exp2(d0);
            __half2 p1 = h2exp2(d1);
            pf[nt][0] = *reinterpret_cast<uint32_t*>(&p0);
            pf[nt][1] = *reinterpret_cast<uint32_t*>(&p1);
            float2 f0 = __half22float2(p0);
            float2 f1 = __half22float2(p1);
            sum0 += f0.x + f0.y;
            sum1 += f1.x + f1.y;
        }
        sum0 += __shfl_xor_sync(0xffffffffu, sum0, 1);
        sum0 += __shfl_xor_sync(0xffffffffu, sum0, 2);
        sum1 += __shfl_xor_sync(0xffffffffu, sum1, 1);
        sum1 += __shfl_xor_sync(0xffffffffu, sum1, 2);
        l0 = l0 * corr0 + sum0;
        l1 = l1 * corr1 + sum1;
        m0 = mn0; m1 = mn1;

        #pragma unroll
        for (int nt = 0; nt < 5; nt++) {
            oacc[nt][0] *= corr0; oacc[nt][1] *= corr0;
            oacc[nt][2] *= corr1; oacc[nt][3] *= corr1;
        }

        #pragma unroll
        for (int ks = 0; ks < 4; ks++) {
            uint32_t af[4] = {pf[2 * ks][0], pf[2 * ks][1],
                              pf[2 * ks + 1][0], pf[2 * ks + 1][1]};
            #pragma unroll
            for (int c0 = 0; c0 < 2; c0++) {
                uint32_t r0, r1, r2, r3;
                uint32_t addr = smem_u32(&vs_[(ks * 16 + krow16) * 56 + c0 * 16 + koff]);
                LDMX4T(r0, r1, r2, r3, addr);
                uint32_t b0[2] = {r0, r1}, b1[2] = {r2, r3};
                MMA_F16(oacc[c0 * 2],     af, b0);
                MMA_F16(oacc[c0 * 2 + 1], af, b1);
            }
            uint32_t r0, r1;
            uint32_t addr = smem_u32(&vs_[(ks * 16 + krow8) * 56 + 32]);
            LDMX2T(r0, r1, addr);
            uint32_t b4[2] = {r0, r1};
            MMA_F16(oacc[4], af, b4);
        }
    }

    float inv0 = 1.f / l0, inv1 = 1.f / l1;
    size_t base0 = (size_t)(q0 + warp * 16 + gid) * D_INNER + h * 40;
    size_t base1 = base0 + 8 * D_INNER;
    #pragma unroll
    for (int nt = 0; nt < 5; nt++) {
        int col = nt * 8 + tig * 2;
        *reinterpret_cast<__half2*>(&o[base0 + col]) = __floats2half2_rn(oacc[nt][0] * inv0, oacc[nt][1] * inv0);
        *reinterpret_cast<__half2*>(&o[base1 + col]) = __floats2half2_rn(oacc[nt][2] * inv1, oacc[nt][3] * inv1);
    }
}

// ---------------- cross-attention: single S pass (smem scores), exp2 ---------
#define CROSS_SMEM ((2 * CTX_LEN * 40 + 128 * 80) * 4)
__global__ __launch_bounds__(128, 2)
void attn_cross_kernel(const __half* __restrict__ q, const __half* __restrict__ k2,
                       const __half* __restrict__ v2, __half* __restrict__ o)
{
    extern __shared__ __half smh[];
    float* Ks = reinterpret_cast<float*>(smh);
    float* Vs = Ks + CTX_LEN * 40;
    float* Sc = Vs + CTX_LEN * 40;

    const int h  = blockIdx.y;
    const int q0 = blockIdx.x * 128;
    const int tid = threadIdx.x;

    for (int idx = tid; idx < CTX_LEN * 40; idx += 128) {
        int r = idx / 40;
        int d = idx - r * 40;
        Ks[idx] = __half2float(k2[r * D_INNER + h * 40 + d]);
        Vs[idx] = __half2float(v2[r * D_INNER + h * 40 + d]);
    }
    __syncthreads();

    float qr[40];
    #pragma unroll
    for (int d = 0; d < 40; d++)
        qr[d] = __half2float(q[(size_t)(q0 + tid) * D_INNER + h * 40 + d]) * QSCALE_L2E;

    float* srow = &Sc[tid * 80];
    float m = -1e30f;
    for (int j = 0; j < CTX_LEN; j++) {
        float s = 0.f;
        #pragma unroll
        for (int d = 0; d < 40; d++) s += qr[d] * Ks[j * 40 + d];
        srow[j] = s;
        m = fmaxf(m, s);
    }
    float l = 0.f;
    float accv[40];
    #pragma unroll
    for (int d = 0; d < 40; d++) accv[d] = 0.f;
    for (int j = 0; j < CTX_LEN; j++) {
        float p = exp2f(srow[j] - m);
        l += p;
        #pragma unroll
        for (int d = 0; d < 40; d++) accv[d] += p * Vs[j * 40 + d];
    }
    float inv = 1.f / l;
    #pragma unroll
    for (int d = 0; d < 40; d++)
        o[(size_t)(q0 + tid) * D_INNER + h * 40 + d] = __float2half(accv[d] * inv);
}

// ---------------- host ----------------
static inline void gemm16(const __half* A, const __half* BT, const float* bias,
                          const float* resid, float* C32, __half* C16,
                          int M, int N, int K, int flags)
{
    dim3 grid(N / GBN, M / GBM);
    gemm_f16_kernel<<<grid, 128, GEMM_SMEM_BYTES>>>(A, BT, bias, resid, C32, C16, M, N, K, flags);
}

extern "C" void kernel_launch(void* const* d_in, const int* in_sizes, int n_in,
                              void* d_out, int out_size)
{
    const float* x          = (const float*)d_in[0];
    const float* context    = (const float*)d_in[1];
    const float* gn_scale   = (const float*)d_in[2];
    const float* gn_bias    = (const float*)d_in[3];
    const float* w_proj_in  = (const float*)d_in[4];
    const float* b_proj_in  = (const float*)d_in[5];
    const float* ln1_s      = (const float*)d_in[6];
    const float* ln1_b      = (const float*)d_in[7];
    const float* wq1        = (const float*)d_in[8];
    const float* wk1        = (const float*)d_in[9];
    const float* wv1        = (const float*)d_in[10];
    const float* wo1        = (const float*)d_in[11];
    const float* bo1        = (const float*)d_in[12];
    const float* ln2_s      = (const float*)d_in[13];
    const float* ln2_b      = (const float*)d_in[14];
    const float* wq2        = (const float*)d_in[15];
    const float* wk2        = (const float*)d_in[16];
    const float* wv2        = (const float*)d_in[17];
    const float* wo2        = (const float*)d_in[18];
    const float* bo2        = (const float*)d_in[19];
    const float* ln3_s      = (const float*)d_in[20];
    const float* ln3_b      = (const float*)d_in[21];
    const float* w_ff1      = (const float*)d_in[22];
    const float* b_ff1      = (const float*)d_in[23];
    const float* w_ff2      = (const float*)d_in[24];
    const float* b_ff2      = (const float*)d_in[25];
    const float* w_proj_out = (const float*)d_in[26];
    const float* b_proj_out = (const float*)d_in[27];
    float* out = (float*)d_out;

    float *h;
    __half *hh, *gn, *hn, *q, *k, *v, *attn, *act, *k2, *v2, *wT;
    cudaGetSymbolAddress((void**)&h,    g_h);
    cudaGetSymbolAddress((void**)&hh,   g_hh);
    cudaGetSymbolAddress((void**)&gn,   g_gn);
    cudaGetSymbolAddress((void**)&hn,   g_hn);
    cudaGetSymbolAddress((void**)&q,    g_q);
    cudaGetSymbolAddress((void**)&k,    g_k);
    cudaGetSymbolAddress((void**)&v,    g_v);
    cudaGetSymbolAddress((void**)&attn, g_at);
    cudaGetSymbolAddress((void**)&act,  g_act);
    cudaGetSymbolAddress((void**)&k2,   g_k2);
    cudaGetSymbolAddress((void**)&v2,   g_v2);
    cudaGetSymbolAddress((void**)&wT,   g_wTh);

    cudaFuncSetAttribute(gemm_f16_kernel, cudaFuncAttributeMaxDynamicSharedMemorySize, GEMM_SMEM_BYTES);
    cudaFuncSetAttribute(gemm_qkv_kernel, cudaFuncAttributeMaxDynamicSharedMemorySize, GEMM_SMEM_BYTES);
    cudaFuncSetAttribute(gemm_ff1g_kernel, cudaFuncAttributeMaxDynamicSharedMemorySize, FF1_SMEM_BYTES);
    cudaFuncSetAttribute(attn_self_f16_kernel, cudaFuncAttributeMaxDynamicSharedMemorySize, ATTN_SMEM_BYTES);
    cudaFuncSetAttribute(attn_cross_kernel, cudaFuncAttributeMaxDynamicSharedMemorySize, CROSS_SMEM);

    __half* t_proj_in  = wT + 0;
    __half* t_wq1      = wT + 102400;
    __half* t_wk1      = wT + 204800;
    __half* t_wv1      = wT + 307200;
    __half* t_wo1      = wT + 409600;
    __half* t_wq2      = wT + 512000;
    __half* t_wk2      = wT + 614400;
    __half* t_wv2      = wT + 860160;
    __half* t_wo2      = wT + 1105920;
    __half* t_ff1      = wT + 1208320;
    __half* t_ff2      = wT + 2027520;
    __half* t_proj_out = wT + 2437120;

    TArgs ta;
    ta.d[0]  = {w_proj_in,  t_proj_in,  320,  320};
    ta.d[1]  = {wq1,        t_wq1,      320,  320};
    ta.d[2]  = {wk1,        t_wk1,      320,  320};
    ta.d[3]  = {wv1,        t_wv1,      320,  320};
    ta.d[4]  = {wo1,        t_wo1,      320,  320};
    ta.d[5]  = {wq2,        t_wq2,      320,  320};
    ta.d[6]  = {wk2,        t_wk2,      768,  320};
    ta.d[7]  = {wv2,        t_wv2,      768,  320};
    ta.d[8]  = {wo2,        t_wo2,      320,  320};
    ta.d[9]  = {w_ff1,      t_ff1,      320,  2560};
    ta.d[10] = {w_ff2,      t_ff2,      1280, 320};
    ta.d[11] = {w_proj_out, t_proj_out, 320,  320};
    ta.off[0] = 0;
    for (int s = 0; s < 12; s++) {
        int tx = (ta.d[s].N + 31) / 32;
        int ty = (ta.d[s].K + 31) / 32;
        ta.off[s + 1] = ta.off[s] + tx * ty;
    }
    transpose_all_kernel<<<ta.off[12], dim3(32, 8)>>>(ta);

    gn_part_kernel<<<dim3(32, 8), 256>>>(x);
    gn_apply_kernel<<<dim3(32, 8), 256>>>(x, gn_scale, gn_bias, gn);
    gemm16(gn, t_proj_in, b_proj_in, nullptr, h, nullptr, S_TOK, D_INNER, D_INNER, 0);

    // --- self attention (Q pre-scaled by ATT_SCALE*log2e in QKV epilogue) ---
    layernorm_kernel<<<S_TOK / 8, 256>>>(h, ln1_s, ln1_b, hn);
    {
        dim3 grid(D_INNER / GBN, S_TOK / GBM, 3);
        gemm_qkv_kernel<<<grid, 128, GEMM_SMEM_BYTES>>>(hn, t_wq1, t_wk1, t_wv1,
                                                        q, k, v, S_TOK, D_INNER, D_INNER);
    }
    attn_self_f16_kernel<<<dim3(S_TOK / 128, HEADS), 256, ATTN_SMEM_BYTES>>>(q, k, v, attn);
    gemm16(attn, t_wo1, bo1, h, h, nullptr, S_TOK, D_INNER, D_INNER, 0);

    // --- cross attention ---
    layernorm_kernel<<<S_TOK / 8, 256>>>(h, ln2_s, ln2_b, hn);
    gemm16(hn, t_wq2, nullptr, nullptr, nullptr, q, S_TOK, D_INNER, D_INNER, 2);
    sgemm_ctx_kernel<<<dim3(D_INNER / BN, (CTX_LEN + BM - 1) / BM, 2), 256>>>(
        context, wk2, wv2, k2, v2, CTX_LEN, D_INNER, CTX_DIM);
    attn_cross_kernel<<<dim3(S_TOK / 128, HEADS), 128, CROSS_SMEM>>>(q, k2, v2, attn);
    gemm16(attn, t_wo2, bo2, h, h, nullptr, S_TOK, D_INNER, D_INNER, 0);

    // --- fused GEGLU feed forward ---
    layernorm_kernel<<<S_TOK / 8, 256>>>(h, ln3_s, ln3_b, hn);
    {
        dim3 grid(FF_HALF / GBN, S_TOK / GBM);
        gemm_ff1g_kernel<<<grid, 128, FF1_SMEM_BYTES>>>(hn, t_ff1, b_ff1, act,
                                                        S_TOK, D_INNER);
    }
    gemm16(act, t_ff2, b_ff2, h, h, hh, S_TOK, D_INNER, FF_HALF, 4);

    // --- proj_out (transposed fp32 store) + input residual ---
    gemm16(hh, t_proj_out, b_proj_out, x, out, nullptr, S_TOK, D_INNER, D_INNER, 1);
}

// round 17
// speedup vs baseline: 1.0213x; 1.0213x over previous
#include <cuda_runtime.h>
#include <cuda_fp16.h>
#include <math.h>
#include <stdint.h>

#define S_TOK   4096
#define D_INNER 320
#define HEADS   8
#define DHEAD   40
#define CTX_LEN 77
#define CTX_DIM 768
#define FF_IN   2560
#define FF_HALF 1280
#define ATT_SCALE 0.15811388300841897f
#define QSCALE_L2E (0.15811388300841897f * 1.4426950408889634f)

// ---------------- scratch ----------------
__device__ float  g_h  [S_TOK * D_INNER];          // fp32 residual stream
__device__ __half g_hh [S_TOK * D_INNER];
__device__ __half g_gn [S_TOK * D_INNER];
__device__ __half g_hn [S_TOK * D_INNER];
__device__ __half g_q  [S_TOK * D_INNER];
__device__ __half g_k  [S_TOK * D_INNER];
__device__ __half g_v  [S_TOK * D_INNER];
__device__ __half g_at [S_TOK * D_INNER];
__device__ __half g_act[S_TOK * FF_HALF];
__device__ __half g_k2 [CTX_LEN * D_INNER];
__device__ __half g_v2 [CTX_LEN * D_INNER];
__device__ __half g_wTh[2539520];                  // all weights half, [n][k]
__device__ float  g_gnp[512];                      // groupnorm partials

#define MMA_F16(c, a, b) \
    asm volatile("mma.sync.aligned.m16n8k16.row.col.f32.f16.f16.f32 " \
                 "{%0,%1,%2,%3},{%4,%5,%6,%7},{%8,%9},{%0,%1,%2,%3};" \
                 : "+f"((c)[0]), "+f"((c)[1]), "+f"((c)[2]), "+f"((c)[3]) \
                 : "r"((a)[0]), "r"((a)[1]), "r"((a)[2]), "r"((a)[3]), \
                   "r"((b)[0]), "r"((b)[1]))

#define MMA_F16_K8(c, a0, a1, b0) \
    asm volatile("mma.sync.aligned.m16n8k8.row.col.f32.f16.f16.f32 " \
                 "{%0,%1,%2,%3},{%4,%5},{%6},{%0,%1,%2,%3};" \
                 : "+f"((c)[0]), "+f"((c)[1]), "+f"((c)[2]), "+f"((c)[3]) \
                 : "r"(a0), "r"(a1), "r"(b0))

#define LDMX4(r0, r1, r2, r3, addr) \
    asm volatile("ldmatrix.sync.aligned.m8n8.x4.shared.b16 {%0,%1,%2,%3}, [%4];" \
                 : "=r"(r0), "=r"(r1), "=r"(r2), "=r"(r3) : "r"(addr))
#define LDMX2(r0, r1, addr) \
    asm volatile("ldmatrix.sync.aligned.m8n8.x2.shared.b16 {%0,%1}, [%2];" \
                 : "=r"(r0), "=r"(r1) : "r"(addr))
#define LDMX4T(r0, r1, r2, r3, addr) \
    asm volatile("ldmatrix.sync.aligned.m8n8.x4.trans.shared.b16 {%0,%1,%2,%3}, [%4];" \
                 : "=r"(r0), "=r"(r1), "=r"(r2), "=r"(r3) : "r"(addr))
#define LDMX2T(r0, r1, addr) \
    asm volatile("ldmatrix.sync.aligned.m8n8.x2.trans.shared.b16 {%0,%1}, [%2];" \
                 : "=r"(r0), "=r"(r1) : "r"(addr))

__device__ __forceinline__ void cp_async16(uint32_t s, const void* g) {
    asm volatile("cp.async.cg.shared.global [%0], [%1], 16;" :: "r"(s), "l"(g));
}
__device__ __forceinline__ void cp_commit() {
    asm volatile("cp.async.commit_group;");
}
template<int W> __device__ __forceinline__ void cp_wait() {
    asm volatile("cp.async.wait_group %0;" :: "n"(W));
}
__device__ __forceinline__ uint32_t smem_u32(const void* p) {
    return (uint32_t)__cvta_generic_to_shared(p);
}
__device__ __forceinline__ uint32_t packh2(float a, float b) {
    __half2 h = __floats2half2_rn(a, b);
    return *reinterpret_cast<uint32_t*>(&h);
}

// ---------------- weight transpose + fp32->half (flat tile grid) -------------
struct TDesc { const float* src; __half* dst; int K; int N; };
struct TArgs { TDesc d[12]; int off[13]; };

__global__ void transpose_all_kernel(TArgs a)
{
    int b = blockIdx.x;
    int s = 0;
    #pragma unroll
    for (int i = 0; i < 12; i++)
        if (b >= a.off[i + 1]) s = i + 1;
    TDesc t = a.d[s];
    int local = b - a.off[s];
    int tilesx = (t.N + 31) >> 5;
    int bx = local % tilesx;
    int by = local / tilesx;

    __shared__ float tile[32][33];
    int tx = threadIdx.x, ty = threadIdx.y;
    int x = bx * 32 + tx;
    int y0 = by * 32;
    #pragma unroll
    for (int j = 0; j < 4; j++) {
        int y = y0 + ty + j * 8;
        if (y < t.K && x < t.N)
            tile[ty + j * 8][tx] = t.src[(size_t)y * t.N + x];
    }
    __syncthreads();
    int x2 = by * 32 + tx;
    int y20 = bx * 32;
    #pragma unroll
    for (int j = 0; j < 4; j++) {
        int y2 = y20 + ty + j * 8;
        if (y2 < t.N && x2 < t.K)
            t.dst[(size_t)y2 * t.K + x2] = __float2half(tile[tx][ty + j * 8]);
    }
}

// ---------------- GroupNorm split: partial sums + apply ----------------------
__global__ void gn_part_kernel(const float* __restrict__ x)
{
    const int g = blockIdx.x, b = blockIdx.y;
    const float4* p = reinterpret_cast<const float4*>(x + g * 10 * S_TOK + b * 5120);
    float s = 0.f, sq = 0.f;
    #pragma unroll
    for (int i = 0; i < 5; i++) {
        float4 v = p[threadIdx.x + i * 256];
        s  += v.x + v.y + v.z + v.w;
        sq += v.x * v.x + v.y * v.y + v.z * v.z + v.w * v.w;
    }
    __shared__ float ss[256], sk[256];
    ss[threadIdx.x] = s; sk[threadIdx.x] = sq;
    __syncthreads();
    for (int off = 128; off > 0; off >>= 1) {
        if (threadIdx.x < off) {
            ss[threadIdx.x] += ss[threadIdx.x + off];
            sk[threadIdx.x] += sk[threadIdx.x + off];
        }
        __syncthreads();
    }
    if (threadIdx.x == 0) {
        g_gnp[(g * 8 + b) * 2]     = ss[0];
        g_gnp[(g * 8 + b) * 2 + 1] = sk[0];
    }
}

__global__ void gn_apply_kernel(const float* __restrict__ x,
                                const float* __restrict__ scale,
                                const float* __restrict__ bias,
                                __half* __restrict__ outT)
{
    const int g = blockIdx.x, b = blockIdx.y;
    float s = 0.f, sq = 0.f;
    #pragma unroll
    for (int i = 0; i < 8; i++) {
        s  += g_gnp[(g * 8 + i) * 2];
        sq += g_gnp[(g * 8 + i) * 2 + 1];
    }
    const float mean = s / 40960.f;
    const float rstd = rsqrtf(sq / 40960.f - mean * mean + 1e-6f);
    const int base = g * 10 * S_TOK + b * 5120;
    const float4* p = reinterpret_cast<const float4*>(x + base);
    #pragma unroll
    for (int i = 0; i < 5; i++) {
        int ii = threadIdx.x + i * 256;
        float4 v = p[ii];
        int idx = base + ii * 4;
        int c = idx >> 12;
        int sp = idx & 4095;
        float sc = scale[c], bi = bias[c];
        outT[(sp + 0) * D_INNER + c] = __float2half((v.x - mean) * rstd * sc + bi);
        outT[(sp + 1) * D_INNER + c] = __float2half((v.y - mean) * rstd * sc + bi);
        outT[(sp + 2) * D_INNER + c] = __float2half((v.z - mean) * rstd * sc + bi);
        outT[(sp + 3) * D_INNER + c] = __float2half((v.w - mean) * rstd * sc + bi);
    }
}

// ---------------- LayerNorm ----------------
__global__ void layernorm_kernel(const float* __restrict__ in,
                                 const float* __restrict__ s,
                                 const float* __restrict__ b,
                                 __half* __restrict__ out)
{
    int row = blockIdx.x * 8 + (threadIdx.x >> 5);
    int lane = threadIdx.x & 31;
    const float2* xr = reinterpret_cast<const float2*>(in + row * D_INNER);
    float2 v[5];
    float sum = 0.f, sq = 0.f;
    #pragma unroll
    for (int i = 0; i < 5; i++) {
        v[i] = xr[lane + i * 32];
        sum += v[i].x + v[i].y;
        sq  += v[i].x * v[i].x + v[i].y * v[i].y;
    }
    #pragma unroll
    for (int off = 16; off > 0; off >>= 1) {
        sum += __shfl_xor_sync(0xffffffffu, sum, off);
        sq  += __shfl_xor_sync(0xffffffffu, sq,  off);
    }
    float mean = sum / (float)D_INNER;
    float var  = sq / (float)D_INNER - mean * mean;
    float rstd = rsqrtf(var + 1e-5f);
    __half2* orow = reinterpret_cast<__half2*>(out + row * D_INNER);
    #pragma unroll
    for (int i = 0; i < 5; i++) {
        int j = (lane + i * 32) * 2;
        float y0 = (v[i].x - mean) * rstd * s[j]     + b[j];
        float y1 = (v[i].y - mean) * rstd * s[j + 1] + b[j + 1];
        orow[lane + i * 32] = __floats2half2_rn(y0, y1);
    }
}

// ---------------- fp16 GEMM: 64x64x32, 128 thr (R11 config) ------------------
#define GBM 64
#define GBN 64
#define GBK 32
#define STG 2560
#define GEMM_SMEM_BYTES (6 * STG * 2)

__device__ __forceinline__ void gemm_core(
    const __half* __restrict__ A, const __half* __restrict__ BT,
    const float* __restrict__ bias, const float* __restrict__ resid,
    float* __restrict__ C32, __half* __restrict__ C16,
    int M, int N, int K, int flags, int bm, int bn, float oscale)
{
    extern __shared__ __half smh[];
    const int tid = threadIdx.x;
    const int warp = tid >> 5, lane = tid & 31;
    const int wm = (warp >> 1) * 32, wn = (warp & 1) * 32;
    const int gid = lane >> 2, tig = lane & 3;

    float c[2][4][4];
    #pragma unroll
    for (int i = 0; i < 2; i++)
        #pragma unroll
        for (int j = 0; j < 4; j++)
            #pragma unroll
            for (int t = 0; t < 4; t++) c[i][j][t] = 0.f;

    const int nk = K / GBK;
    const int lr = tid >> 2;
    const int lc = (tid & 3) * 8;

    auto load_stage = [&](int s, int k0) {
        #pragma unroll
        for (int i = 0; i < 2; i++) {
            int r = lr + i * 32;
            cp_async16(smem_u32(&smh[s * STG + r * 40 + lc]),
                       A + (size_t)(bm + r) * K + k0 + lc);
        }
        #pragma unroll
        for (int i = 0; i < 2; i++) {
            int r = lr + i * 32;
            cp_async16(smem_u32(&smh[3 * STG + s * STG + r * 40 + lc]),
                       BT + (size_t)(bn + r) * K + k0 + lc);
        }
    };

    load_stage(0, 0); cp_commit();
    load_stage(1, GBK); cp_commit();

    const int a_row = wm + (lane & 15);
    const int koff  = (lane >> 4) * 8;

    for (int t = 0; t < nk; t++) {
        cp_wait<1>();
        __syncthreads();
        if (t + 2 < nk) load_stage((t + 2) % 3, (t + 2) * GBK);
        cp_commit();

        const int s = t % 3;
        __half* as = &smh[s * STG];
        __half* bs = &smh[3 * STG + s * STG];

        #pragma unroll
        for (int ks = 0; ks < 2; ks++) {
            uint32_t af[2][4], bf[4][2];
            #pragma unroll
            for (int mt = 0; mt < 2; mt++) {
                uint32_t addr = smem_u32(&as[(a_row + mt * 16) * 40 + ks * 16 + koff]);
                LDMX4(af[mt][0], af[mt][1], af[mt][2], af[mt][3], addr);
            }
            #pragma unroll
            for (int p = 0; p < 2; p++) {
                uint32_t r0, r1, r2, r3;
                uint32_t addr = smem_u32(&bs[(wn + p * 16 + (lane & 15)) * 40 + ks * 16 + koff]);
                LDMX4(r0, r1, r2, r3, addr);
                bf[2 * p][0]     = r0; bf[2 * p][1]     = r2;
                bf[2 * p + 1][0] = r1; bf[2 * p + 1][1] = r3;
            }
            #pragma unroll
            for (int mt = 0; mt < 2; mt++)
                #pragma unroll
                for (int nt = 0; nt < 4; nt++)
                    MMA_F16(c[mt][nt], af[mt], bf[nt]);
        }
    }

    #pragma unroll
    for (int mt = 0; mt < 2; mt++) {
        int r0 = bm + wm + mt * 16 + gid;
        int r1 = r0 + 8;
        #pragma unroll
        for (int nt = 0; nt < 4; nt++) {
            int col = bn + wn + nt * 8 + tig * 2;
            float v00 = c[mt][nt][0], v01 = c[mt][nt][1];
            float v10 = c[mt][nt][2], v11 = c[mt][nt][3];
            if (bias) {
                float b0 = bias[col], b1 = bias[col + 1];
                v00 += b0; v01 += b1; v10 += b0; v11 += b1;
            }
            if (flags & 2) {
                v00 *= oscale; v01 *= oscale; v10 *= oscale; v11 *= oscale;
                *reinterpret_cast<__half2*>(&C16[(size_t)r0 * N + col]) = __floats2half2_rn(v00, v01);
                *reinterpret_cast<__half2*>(&C16[(size_t)r1 * N + col]) = __floats2half2_rn(v10, v11);
            } else if (flags & 1) {
                if (resid) {
                    v00 += resid[(size_t)col * M + r0];
                    v01 += resid[(size_t)(col + 1) * M + r0];
                    v10 += resid[(size_t)col * M + r1];
                    v11 += resid[(size_t)(col + 1) * M + r1];
                }
                C32[(size_t)col * M + r0]       = v00;
                C32[(size_t)(col + 1) * M + r0] = v01;
                C32[(size_t)col * M + r1]       = v10;
                C32[(size_t)(col + 1) * M + r1] = v11;
            } else {
                if (resid) {
                    v00 += resid[(size_t)r0 * N + col];
                    v01 += resid[(size_t)r0 * N + col + 1];
                    v10 += resid[(size_t)r1 * N + col];
                    v11 += resid[(size_t)r1 * N + col + 1];
                }
                C32[(size_t)r0 * N + col]     = v00;
                C32[(size_t)r0 * N + col + 1] = v01;
                C32[(size_t)r1 * N + col]     = v10;
                C32[(size_t)r1 * N + col + 1] = v11;
                if (flags & 4) {
                    *reinterpret_cast<__half2*>(&C16[(size_t)r0 * N + col]) = __floats2half2_rn(v00, v01);
                    *reinterpret_cast<__half2*>(&C16[(size_t)r1 * N + col]) = __floats2half2_rn(v10, v11);
                }
            }
        }
    }
}

__global__ __launch_bounds__(128)
void gemm_f16_kernel(const __half* __restrict__ A, const __half* __restrict__ BT,
                     const float* __restrict__ bias, const float* __restrict__ resid,
                     float* __restrict__ C32, __half* __restrict__ C16,
                     int M, int N, int K, int flags)
{
    gemm_core(A, BT, bias, resid, C32, C16, M, N, K, flags,
              blockIdx.y * GBM, blockIdx.x * GBN, 1.0f);
}

__global__ __launch_bounds__(128)
void gemm_qkv_kernel(const __half* __restrict__ A,
                     const __half* __restrict__ B0, const __half* __restrict__ B1,
                     const __half* __restrict__ B2,
                     __half* __restrict__ C0, __half* __restrict__ C1,
                     __half* __restrict__ C2, int M, int N, int K)
{
    const __half* B = (blockIdx.z == 0) ? B0 : (blockIdx.z == 1) ? B1 : B2;
    __half* C       = (blockIdx.z == 0) ? C0 : (blockIdx.z == 1) ? C1 : C2;
    float oscale    = (blockIdx.z == 0) ? QSCALE_L2E : 1.0f;
    gemm_core(A, B, nullptr, nullptr, nullptr, C, M, N, K, 2,
              blockIdx.y * GBM, blockIdx.x * GBN, oscale);
}

// ---------------- fused ff1 + GEGLU (128 thr) --------------------------------
#define FF1_SMEM_BYTES (9 * STG * 2)
__global__ __launch_bounds__(128)
void gemm_ff1g_kernel(const __half* __restrict__ A, const __half* __restrict__ BT,
                      const float* __restrict__ bias, __half* __restrict__ act,
                      int M, int K)
{
    extern __shared__ __half smh[];
    const int bm = blockIdx.y * GBM;
    const int bn = blockIdx.x * GBN;
    const int tid = threadIdx.x;
    const int warp = tid >> 5, lane = tid & 31;
    const int wm = (warp >> 1) * 32, wn = (warp & 1) * 32;
    const int gid = lane >> 2, tig = lane & 3;

    float ca[2][4][4], cg[2][4][4];
    #pragma unroll
    for (int i = 0; i < 2; i++)
        #pragma unroll
        for (int j = 0; j < 4; j++)
            #pragma unroll
            for (int t = 0; t < 4; t++) { ca[i][j][t] = 0.f; cg[i][j][t] = 0.f; }

    const int nk = K / GBK;
    const int lr = tid >> 2;
    const int lc = (tid & 3) * 8;

    auto load_stage = [&](int s, int k0) {
        #pragma unroll
        for (int i = 0; i < 2; i++) {
            int r = lr + i * 32;
            cp_async16(smem_u32(&smh[s * STG + r * 40 + lc]),
                       A + (size_t)(bm + r) * K + k0 + lc);
            cp_async16(smem_u32(&smh[3 * STG + s * STG + r * 40 + lc]),
                       BT + (size_t)(bn + r) * K + k0 + lc);
            cp_async16(smem_u32(&smh[6 * STG + s * STG + r * 40 + lc]),
                       BT + (size_t)(FF_HALF + bn + r) * K + k0 + lc);
        }
    };

    load_stage(0, 0); cp_commit();
    load_stage(1, GBK); cp_commit();

    const int a_row = wm + (lane & 15);
    const int koff  = (lane >> 4) * 8;

    for (int t = 0; t < nk; t++) {
        cp_wait<1>();
        __syncthreads();
        if (t + 2 < nk) load_stage((t + 2) % 3, (t + 2) * GBK);
        cp_commit();

        const int s = t % 3;
        __half* as  = &smh[s * STG];
        __half* bsa = &smh[3 * STG + s * STG];
        __half* bsg = &smh[6 * STG + s * STG];

        #pragma unroll
        for (int ks = 0; ks < 2; ks++) {
            uint32_t af[2][4], bfa[4][2], bfg[4][2];
            #pragma unroll
            for (int mt = 0; mt < 2; mt++) {
                uint32_t addr = smem_u32(&as[(a_row + mt * 16) * 40 + ks * 16 + koff]);
                LDMX4(af[mt][0], af[mt][1], af[mt][2], af[mt][3], addr);
            }
            #pragma unroll
            for (int p = 0; p < 2; p++) {
                uint32_t r0, r1, r2, r3;
                uint32_t addr = smem_u32(&bsa[(wn + p * 16 + (lane & 15)) * 40 + ks * 16 + koff]);
                LDMX4(r0, r1, r2, r3, addr);
                bfa[2 * p][0] = r0; bfa[2 * p][1] = r2;
                bfa[2 * p + 1][0] = r1; bfa[2 * p + 1][1] = r3;
                addr = smem_u32(&bsg[(wn + p * 16 + (lane & 15)) * 40 + ks * 16 + koff]);
                LDMX4(r0, r1, r2, r3, addr);
                bfg[2 * p][0] = r0; bfg[2 * p][1] = r2;
                bfg[2 * p + 1][0] = r1; bfg[2 * p + 1][1] = r3;
            }
            #pragma unroll
            for (int mt = 0; mt < 2; mt++)
                #pragma unroll
                for (int nt = 0; nt < 4; nt++) {
                    MMA_F16(ca[mt][nt], af[mt], bfa[nt]);
                    MMA_F16(cg[mt][nt], af[mt], bfg[nt]);
                }
        }
    }

    #pragma unroll
    for (int mt = 0; mt < 2; mt++) {
        int r0 = bm + wm + mt * 16 + gid;
        int r1 = r0 + 8;
        #pragma unroll
        for (int nt = 0; nt < 4; nt++) {
            int col = bn + wn + nt * 8 + tig * 2;
            float ba0 = bias[col], ba1 = bias[col + 1];
            float bg0 = bias[FF_HALF + col], bg1 = bias[FF_HALF + col + 1];
            float a00 = ca[mt][nt][0] + ba0, a01 = ca[mt][nt][1] + ba1;
            float a10 = ca[mt][nt][2] + ba0, a11 = ca[mt][nt][3] + ba1;
            float g00 = cg[mt][nt][0] + bg0, g01 = cg[mt][nt][1] + bg1;
            float g10 = cg[mt][nt][2] + bg0, g11 = cg[mt][nt][3] + bg1;
            const float inv_s2 = 0.70710678118654752f;
            float e00 = 0.5f * g00 * (1.f + erff(g00 * inv_s2));
            float e01 = 0.5f * g01 * (1.f + erff(g01 * inv_s2));
            float e10 = 0.5f * g10 * (1.f + erff(g10 * inv_s2));
            float e11 = 0.5f * g11 * (1.f + erff(g11 * inv_s2));
            *reinterpret_cast<__half2*>(&act[(size_t)r0 * FF_HALF + col]) =
                __floats2half2_rn(a00 * e00, a01 * e01);
            *reinterpret_cast<__half2*>(&act[(size_t)r1 * FF_HALF + col]) =
                __floats2half2_rn(a10 * e10, a11 * e11);
        }
    }
}

// ---------------- fp32 SGEMM for ctx K/V (small M=77), half out -------------
#define BM 64
#define BN 64
#define BKK 16
__global__ __launch_bounds__(256)
void sgemm_ctx_kernel(const float* __restrict__ A,
                      const float* __restrict__ B0, const float* __restrict__ B1,
                      __half* __restrict__ C0, __half* __restrict__ C1,
                      int M, int N, int K)
{
    const float* B = (blockIdx.z == 0) ? B0 : B1;
    __half* C      = (blockIdx.z == 0) ? C0 : C1;
    __shared__ float As[BKK][BM];
    __shared__ float Bs[BKK][BN];
    const int bm = blockIdx.y * BM;
    const int bn = blockIdx.x * BN;
    const int tid = threadIdx.x;
    const int tx = tid & 15;
    const int ty = tid >> 4;
    const int arow = tid >> 2;
    const int acol = (tid & 3) * 4;
    const int brow = tid >> 4;
    const int bcol = (tid & 15) * 4;

    float acc[4][4];
    #pragma unroll
    for (int i = 0; i < 4; i++)
        #pragma unroll
        for (int j = 0; j < 4; j++) acc[i][j] = 0.f;

    for (int k0 = 0; k0 < K; k0 += BKK) {
        float4 av = make_float4(0.f, 0.f, 0.f, 0.f);
        if (bm + arow < M)
            av = *reinterpret_cast<const float4*>(A + (size_t)(bm + arow) * K + k0 + acol);
        As[acol + 0][arow] = av.x;
        As[acol + 1][arow] = av.y;
        As[acol + 2][arow] = av.z;
        As[acol + 3][arow] = av.w;
        float4 bv = *reinterpret_cast<const float4*>(B + (size_t)(k0 + brow) * N + bn + bcol);
        *reinterpret_cast<float4*>(&Bs[brow][bcol]) = bv;
        __syncthreads();
        #pragma unroll
        for (int kk = 0; kk < BKK; kk++) {
            float4 a4 = *reinterpret_cast<const float4*>(&As[kk][ty * 4]);
            float4 b4 = *reinterpret_cast<const float4*>(&Bs[kk][tx * 4]);
            float a[4] = {a4.x, a4.y, a4.z, a4.w};
            float b[4] = {b4.x, b4.y, b4.z, b4.w};
            #pragma unroll
            for (int i = 0; i < 4; i++)
                #pragma unroll
                for (int j = 0; j < 4; j++)
                    acc[i][j] += a[i] * b[j];
        }
        __syncthreads();
    }

    #pragma unroll
    for (int i = 0; i < 4; i++) {
        int m = bm + ty * 4 + i;
        if (m >= M) continue;
        #pragma unroll
        for (int j = 0; j < 4; j++)
            C[(size_t)m * N + bn + tx * 4 + j] = __float2half(acc[i][j]);
    }
}

// ---------------- self-attention: flash fp16, register P, exp2 softmax -------
#define KS_STG 3584
#define VS_BASE 7168
#define ATTN_SMEM_BYTES (14336 * 2)

__global__ __launch_bounds__(256, 2)
void attn_self_f16_kernel(const __half* __restrict__ q, const __half* __restrict__ k,
                          const __half* __restrict__ v, __half* __restrict__ o)
{
    extern __shared__ __half smh[];

    const int h = blockIdx.y;
    const int q0 = blockIdx.x * 128;
    const int tid = threadIdx.x;
    const int warp = tid >> 5, lane = tid & 31;
    const int gid = lane >> 2, tig = lane & 3;

    uint32_t qf16[2][4], qf8[2];
    {
        const __half* qp0 = q + (size_t)(q0 + warp * 16 + gid) * D_INNER + h * 40;
        const __half* qp1 = qp0 + 8 * D_INNER;
        #pragma unroll
        for (int s = 0; s < 2; s++) {
            qf16[s][0] = *reinterpret_cast<const uint32_t*>(qp0 + s * 16 + 2 * tig);
            qf16[s][1] = *reinterpret_cast<const uint32_t*>(qp1 + s * 16 + 2 * tig);
            qf16[s][2] = *reinterpret_cast<const uint32_t*>(qp0 + s * 16 + 8 + 2 * tig);
            qf16[s][3] = *reinterpret_cast<const uint32_t*>(qp1 + s * 16 + 8 + 2 * tig);
        }
        qf8[0] = *reinterpret_cast<const uint32_t*>(qp0 + 32 + 2 * tig);
        qf8[1] = *reinterpret_cast<const uint32_t*>(qp1 + 32 + 2 * tig);
    }

    float oacc[5][4];
    #pragma unroll
    for (int nt = 0; nt < 5; nt++)
        #pragma unroll
        for (int t = 0; t < 4; t++) oacc[nt][t] = 0.f;
    float m0 = -1e30f, m1 = -1e30f, l0 = 0.f, l1 = 0.f;

    auto load_tile = [&](int buf, int t0) {
        #pragma unroll
        for (int j = 0; j < 2; j++) {
            int i = tid + j * 256;
            if (i < 320) {
                int row = i / 5;
                int c8 = (i - row * 5) * 8;
                size_t gi = (size_t)(t0 + row) * D_INNER + h * 40 + c8;
                cp_async16(smem_u32(&smh[buf * KS_STG + row * 56 + c8]), k + gi);
                cp_async16(smem_u32(&smh[VS_BASE + buf * KS_STG + row * 56 + c8]), v + gi);
            }
        }
    };

    load_tile(0, 0); cp_commit();

    const int NTILES = S_TOK / 64;
    for (int t = 0; t < NTILES; t++) {
        cp_wait<0>();
        __syncthreads();
        if (t + 1 < NTILES) load_tile((t + 1) & 1, (t + 1) * 64);
        cp_commit();

        const __half* ks_ = &smh[(t & 1) * KS_STG];
        const __half* vs_ = &smh[VS_BASE + (t & 1) * KS_STG];

        float sc[8][4];
        #pragma unroll
        for (int nt = 0; nt < 8; nt++)
            #pragma unroll
            for (int e = 0; e < 4; e++) sc[nt][e] = 0.f;

        const int krow16 = lane & 15;
        const int koff   = (lane >> 4) << 3;
        const int krow8  = (lane & 7) + ((lane >> 3) & 1) * 8;
        #pragma unroll
        for (int p = 0; p < 4; p++) {
            #pragma unroll
            for (int s = 0; s < 2; s++) {
                uint32_t r0, r1, r2, r3;
                uint32_t addr = smem_u32(&ks_[(p * 16 + krow16) * 56 + s * 16 + koff]);
                LDMX4(r0, r1, r2, r3, addr);
                uint32_t b0[2] = {r0, r2}, b1[2] = {r1, r3};
                MMA_F16(sc[2 * p],     qf16[s], b0);
                MMA_F16(sc[2 * p + 1], qf16[s], b1);
            }
            uint32_t r0, r1;
            uint32_t addr = smem_u32(&ks_[(p * 16 + krow8) * 56 + 32]);
            LDMX2(r0, r1, addr);
            MMA_F16_K8(sc[2 * p],     qf8[0], qf8[1], r0);
            MMA_F16_K8(sc[2 * p + 1], qf8[0], qf8[1], r1);
        }

        // ---- online softmax (register, dual-accumulator ILP) ----
        float t0a = -1e30f, t0b = -1e30f, t1a = -1e30f, t1b = -1e30f;
        #pragma unroll
        for (int nt = 0; nt < 8; nt += 2) {
            t0a = fmaxf(t0a, fmaxf(sc[nt][0],     sc[nt][1]));
            t0b = fmaxf(t0b, fmaxf(sc[nt + 1][0], sc[nt + 1][1]));
            t1a = fmaxf(t1a, fmaxf(sc[nt][2],     sc[nt][3]));
            t1b = fmaxf(t1b, fmaxf(sc[nt + 1][2], sc[nt + 1][3]));
        }
        float t0m = fmaxf(t0a, t0b), t1m = fmaxf(t1a, t1b);
        t0m = fmaxf(t0m, __shfl_xor_sync(0xffffffffu, t0m, 1));
        t0m = fmaxf(t0m, __shfl_xor_sync(0xffffffffu, t0m, 2));
        t1m = fmaxf(t1m, __shfl_xor_sync(0xffffffffu, t1m, 1));
        t1m = fmaxf(t1m, __shfl_xor_sync(0xffffffffu, t1m, 2));

        float mn0 = fmaxf(m0, t0m), mn1 = fmaxf(m1, t1m);
        float corr0 = exp2f(m0 - mn0), corr1 = exp2f(m1 - mn1);
        float s0a = 0.f, s0b = 0.f, s1a = 0.f, s1b = 0.f;
        uint32_t pf[8][2];
        #pragma unroll
        for (int nt = 0; nt < 8; nt++) {
            float p00 = exp2f(sc[nt][0] - mn0);
            float p01 = exp2f(sc[nt][1] - mn0);
            float p10 = exp2f(sc[nt][2] - mn1);
            float p11 = exp2f(sc[nt][3] - mn1);
            s0a += p00; s0b += p01;
            s1a += p10; s1b += p11;
            pf[nt][0] = packh2(p00, p01);
            pf[nt][1] = packh2(p10, p11);
        }
        float sum0 = s0a + s0b, sum1 = s1a + s1b;
        sum0 += __shfl_xor_sync(0xffffffffu, sum0, 1);
        sum0 += __shfl_xor_sync(0xffffffffu, sum0, 2);
        sum1 += __shfl_xor_sync(0xffffffffu, sum1, 1);
        sum1 += __shfl_xor_sync(0xffffffffu, sum1, 2);
        l0 = l0 * corr0 + sum0;
        l1 = l1 * corr1 + sum1;
        m0 = mn0; m1 = mn1;

        #pragma unroll
        for (int nt = 0; nt < 5; nt++) {
            oacc[nt][0] *= corr0; oacc[nt][1] *= corr0;
            oacc[nt][2] *= corr1; oacc[nt][3] *= corr1;
        }

        #pragma unroll
        for (int ks = 0; ks < 4; ks++) {
            uint32_t af[4] = {pf[2 * ks][0], pf[2 * ks][1],
                              pf[2 * ks + 1][0], pf[2 * ks + 1][1]};
            #pragma unroll
            for (int c0 = 0; c0 < 2; c0++) {
                uint32_t r0, r1, r2, r3;
                uint32_t addr = smem_u32(&vs_[(ks * 16 + krow16) * 56 + c0 * 16 + koff]);
                LDMX4T(r0, r1, r2, r3, addr);
                uint32_t b0[2] = {r0, r1}, b1[2] = {r2, r3};
                MMA_F16(oacc[c0 * 2],     af, b0);
                MMA_F16(oacc[c0 * 2 + 1], af, b1);
            }
            uint32_t r0, r1;
            uint32_t addr = smem_u32(&vs_[(ks * 16 + krow8) * 56 + 32]);
            LDMX2T(r0, r1, addr);
            uint32_t b4[2] = {r0, r1};
            MMA_F16(oacc[4], af, b4);
        }
    }

    float inv0 = 1.f / l0, inv1 = 1.f / l1;
    size_t base0 = (size_t)(q0 + warp * 16 + gid) * D_INNER + h * 40;
    size_t base1 = base0 + 8 * D_INNER;
    #pragma unroll
    for (int nt = 0; nt < 5; nt++) {
        int col = nt * 8 + tig * 2;
        *reinterpret_cast<__half2*>(&o[base0 + col]) = __floats2half2_rn(oacc[nt][0] * inv0, oacc[nt][1] * inv0);
        *reinterpret_cast<__half2*>(&o[base1 + col]) = __floats2half2_rn(oacc[nt][2] * inv1, oacc[nt][3] * inv1);
    }
}

// ---------------- cross-attention: single S pass (smem scores), exp2 ---------
#define CROSS_SMEM ((2 * CTX_LEN * 40 + 128 * 80) * 4)
__global__ __launch_bounds__(128, 2)
void attn_cross_kernel(const __half* __restrict__ q, const __half* __restrict__ k2,
                       const __half* __restrict__ v2, __half* __restrict__ o)
{
    extern __shared__ __half smh[];
    float* Ks = reinterpret_cast<float*>(smh);
    float* Vs = Ks + CTX_LEN * 40;
    float* Sc = Vs + CTX_LEN * 40;

    const int h  = blockIdx.y;
    const int q0 = blockIdx.x * 128;
    const int tid = threadIdx.x;

    for (int idx = tid; idx < CTX_LEN * 40; idx += 128) {
        int r = idx / 40;
        int d = idx - r * 40;
        Ks[idx] = __half2float(k2[r * D_INNER + h * 40 + d]);
        Vs[idx] = __half2float(v2[r * D_INNER + h * 40 + d]);
    }
    __syncthreads();

    float qr[40];
    #pragma unroll
    for (int d = 0; d < 40; d++)
        qr[d] = __half2float(q[(size_t)(q0 + tid) * D_INNER + h * 40 + d]) * QSCALE_L2E;

    float* srow = &Sc[tid * 80];
    float m = -1e30f;
    for (int j = 0; j < CTX_LEN; j++) {
        float s = 0.f;
        #pragma unroll
        for (int d = 0; d < 40; d++) s += qr[d] * Ks[j * 40 + d];
        srow[j] = s;
        m = fmaxf(m, s);
    }
    float l = 0.f;
    float accv[40];
    #pragma unroll
    for (int d = 0; d < 40; d++) accv[d] = 0.f;
    for (int j = 0; j < CTX_LEN; j++) {
        float p = exp2f(srow[j] - m);
        l += p;
        #pragma unroll
        for (int d = 0; d < 40; d++) accv[d] += p * Vs[j * 40 + d];
    }
    float inv = 1.f / l;
    #pragma unroll
    for (int d = 0; d < 40; d++)
        o[(size_t)(q0 + tid) * D_INNER + h * 40 + d] = __float2half(accv[d] * inv);
}

// ---------------- host ----------------
static inline void gemm16(const __half* A, const __half* BT, const float* bias,
                          const float* resid, float* C32, __half* C16,
                          int M, int N, int K, int flags)
{
    dim3 grid(N / GBN, M / GBM);
    gemm_f16_kernel<<<grid, 128, GEMM_SMEM_BYTES>>>(A, BT, bias, resid, C32, C16, M, N, K, flags);
}

extern "C" void kernel_launch(void* const* d_in, const int* in_sizes, int n_in,
                              void* d_out, int out_size)
{
    const float* x          = (const float*)d_in[0];
    const float* context    = (const float*)d_in[1];
    const float* gn_scale   = (const float*)d_in[2];
    const float* gn_bias    = (const float*)d_in[3];
    const float* w_proj_in  = (const float*)d_in[4];
    const float* b_proj_in  = (const float*)d_in[5];
    const float* ln1_s      = (const float*)d_in[6];
    const float* ln1_b      = (const float*)d_in[7];
    const float* wq1        = (const float*)d_in[8];
    const float* wk1        = (const float*)d_in[9];
    const float* wv1        = (const float*)d_in[10];
    const float* wo1        = (const float*)d_in[11];
    const float* bo1        = (const float*)d_in[12];
    const float* ln2_s      = (const float*)d_in[13];
    const float* ln2_b      = (const float*)d_in[14];
    const float* wq2        = (const float*)d_in[15];
    const float* wk2        = (const float*)d_in[16];
    const float* wv2        = (const float*)d_in[17];
    const float* wo2        = (const float*)d_in[18];
    const float* bo2        = (const float*)d_in[19];
    const float* ln3_s      = (const float*)d_in[20];
    const float* ln3_b      = (const float*)d_in[21];
    const float* w_ff1      = (const float*)d_in[22];
    const float* b_ff1      = (const float*)d_in[23];
    const float* w_ff2      = (const float*)d_in[24];
    const float* b_ff2      = (const float*)d_in[25];
    const float* w_proj_out = (const float*)d_in[26];
    const float* b_proj_out = (const float*)d_in[27];
    float* out = (float*)d_out;

    float *h;
    __half *hh, *gn, *hn, *q, *k, *v, *attn, *act, *k2, *v2, *wT;
    cudaGetSymbolAddress((void**)&h,    g_h);
    cudaGetSymbolAddress((void**)&hh,   g_hh);
    cudaGetSymbolAddress((void**)&gn,   g_gn);
    cudaGetSymbolAddress((void**)&hn,   g_hn);
    cudaGetSymbolAddress((void**)&q,    g_q);
    cudaGetSymbolAddress((void**)&k,    g_k);
    cudaGetSymbolAddress((void**)&v,    g_v);
    cudaGetSymbolAddress((void**)&attn, g_at);
    cudaGetSymbolAddress((void**)&act,  g_act);
    cudaGetSymbolAddress((void**)&k2,   g_k2);
    cudaGetSymbolAddress((void**)&v2,   g_v2);
    cudaGetSymbolAddress((void**)&wT,   g_wTh);

    cudaFuncSetAttribute(gemm_f16_kernel, cudaFuncAttributeMaxDynamicSharedMemorySize, GEMM_SMEM_BYTES);
    cudaFuncSetAttribute(gemm_qkv_kernel, cudaFuncAttributeMaxDynamicSharedMemorySize, GEMM_SMEM_BYTES);
    cudaFuncSetAttribute(gemm_ff1g_kernel, cudaFuncAttributeMaxDynamicSharedMemorySize, FF1_SMEM_BYTES);
    cudaFuncSetAttribute(attn_self_f16_kernel, cudaFuncAttributeMaxDynamicSharedMemorySize, ATTN_SMEM_BYTES);
    cudaFuncSetAttribute(attn_cross_kernel, cudaFuncAttributeMaxDynamicSharedMemorySize, CROSS_SMEM);

    __half* t_proj_in  = wT + 0;
    __half* t_wq1      = wT + 102400;
    __half* t_wk1      = wT + 204800;
    __half* t_wv1      = wT + 307200;
    __half* t_wo1      = wT + 409600;
    __half* t_wq2      = wT + 512000;
    __half* t_wk2      = wT + 614400;
    __half* t_wv2      = wT + 860160;
    __half* t_wo2      = wT + 1105920;
    __half* t_ff1      = wT + 1208320;
    __half* t_ff2      = wT + 2027520;
    __half* t_proj_out = wT + 2437120;

    TArgs ta;
    ta.d[0]  = {w_proj_in,  t_proj_in,  320,  320};
    ta.d[1]  = {wq1,        t_wq1,      320,  320};
    ta.d[2]  = {wk1,        t_wk1,      320,  320};
    ta.d[3]  = {wv1,        t_wv1,      320,  320};
    ta.d[4]  = {wo1,        t_wo1,      320,  320};
    ta.d[5]  = {wq2,        t_wq2,      320,  320};
    ta.d[6]  = {wk2,        t_wk2,      768,  320};
    ta.d[7]  = {wv2,        t_wv2,      768,  320};
    ta.d[8]  = {wo2,        t_wo2,      320,  320};
    ta.d[9]  = {w_ff1,      t_ff1,      320,  2560};
    ta.d[10] = {w_ff2,      t_ff2,      1280, 320};
    ta.d[11] = {w_proj_out, t_proj_out, 320,  320};
    ta.off[0] = 0;
    for (int s = 0; s < 12; s++) {
        int tx = (ta.d[s].N + 31) / 32;
        int ty = (ta.d[s].K + 31) / 32;
        ta.off[s + 1] = ta.off[s] + tx * ty;
    }
    transpose_all_kernel<<<ta.off[12], dim3(32, 8)>>>(ta);

    gn_part_kernel<<<dim3(32, 8), 256>>>(x);
    gn_apply_kernel<<<dim3(32, 8), 256>>>(x, gn_scale, gn_bias, gn);
    gemm16(gn, t_proj_in, b_proj_in, nullptr, h, nullptr, S_TOK, D_INNER, D_INNER, 0);

    // --- self attention (Q pre-scaled by ATT_SCALE*log2e in QKV epilogue) ---
    layernorm_kernel<<<S_TOK / 8, 256>>>(h, ln1_s, ln1_b, hn);
    {
        dim3 grid(D_INNER / GBN, S_TOK / GBM, 3);
        gemm_qkv_kernel<<<grid, 128, GEMM_SMEM_BYTES>>>(hn, t_wq1, t_wk1, t_wv1,
                                                        q, k, v, S_TOK, D_INNER, D_INNER);
    }
    attn_self_f16_kernel<<<dim3(S_TOK / 128, HEADS), 256, ATTN_SMEM_BYTES>>>(q, k, v, attn);
    gemm16(attn, t_wo1, bo1, h, h, nullptr, S_TOK, D_INNER, D_INNER, 0);

    // --- cross attention ---
    layernorm_kernel<<<S_TOK / 8, 256>>>(h, ln2_s, ln2_b, hn);
    gemm16(hn, t_wq2, nullptr, nullptr, nullptr, q, S_TOK, D_INNER, D_INNER, 2);
    sgemm_ctx_kernel<<<dim3(D_INNER / BN, (CTX_LEN + BM - 1) / BM, 2), 256>>>(
        context, wk2, wv2, k2, v2, CTX_LEN, D_INNER, CTX_DIM);
    attn_cross_kernel<<<dim3(S_TOK / 128, HEADS), 128, CROSS_SMEM>>>(q, k2, v2, attn);
    gemm16(attn, t_wo2, bo2, h, h, nullptr, S_TOK, D_INNER, D_INNER, 0);

    // --- fused GEGLU feed forward ---
    layernorm_kernel<<<S_TOK / 8, 256>>>(h, ln3_s, ln3_b, hn);
    {
        dim3 grid(FF_HALF / GBN, S_TOK / GBM);
        gemm_ff1g_kernel<<<grid, 128, FF1_SMEM_BYTES>>>(hn, t_ff1, b_ff1, act,
                                                        S_TOK, D_INNER);
    }
    gemm16(act, t_ff2, b_ff2, h, h, hh, S_TOK, D_INNER, FF_HALF, 4);

    // --- proj_out (transposed fp32 store) + input residual ---
    gemm16(hh, t_proj_out, b_proj_out, x, out, nullptr, S_TOK, D_INNER, D_INNER, 1);
}